// round 10
// baseline (speedup 1.0000x reference)
#include <cuda_runtime.h>
#include <math.h>

#define MAXDIM 1024
#define NT 256
#define NW 8
#define POOLSZ 65536

// Scratch (device globals; no allocation allowed)
__device__ float g_Dm[MAXDIM * MAXDIM];   // symmetric merged-distance matrix
__device__ int   g_pool[POOLSZ];          // leaf-list pool (capacity-doubling extents)
__device__ float g_vals[MAXDIM];
__device__ int   g_idx[MAXDIM];
__device__ unsigned g_msim;               // flip-encoded max(X)
__device__ unsigned g_mabs;               // flip-encoded max|X|

__device__ __forceinline__ unsigned fflip(float f) {
    unsigned u = __float_as_uint(f);
    return (u & 0x80000000u) ? ~u : (u | 0x80000000u);
}
__device__ __forceinline__ float funflip(unsigned u) {
    return __uint_as_float((u & 0x80000000u) ? (u & 0x7FFFFFFFu) : ~u);
}

__global__ void k_reset() { g_msim = 0u; g_mabs = 0u; }

__global__ void k_maxred(const float* __restrict__ X, int n) {
    float mx = -3.402823466e38f, ma = 0.f;
    for (int i = blockIdx.x * blockDim.x + threadIdx.x; i < n; i += gridDim.x * blockDim.x) {
        float x = X[i];
        mx = fmaxf(mx, x);
        ma = fmaxf(ma, fabsf(x));
    }
    #pragma unroll
    for (int o = 16; o; o >>= 1) {
        mx = fmaxf(mx, __shfl_down_sync(~0u, mx, o));
        ma = fmaxf(ma, __shfl_down_sync(~0u, ma, o));
    }
    __shared__ float smx[8], sma[8];
    int w = threadIdx.x >> 5, l = threadIdx.x & 31;
    if (l == 0) { smx[w] = mx; sma[w] = ma; }
    __syncthreads();
    if (threadIdx.x == 0) {
        int nw = blockDim.x >> 5;
        for (int i = 1; i < nw; i++) { mx = fmaxf(mx, smx[i]); ma = fmaxf(ma, sma[i]); }
        atomicMax(&g_msim, fflip(mx));
        atomicMax(&g_mabs, fflip(ma));
    }
}

// One block per row r: build Dsym row, R row (identity), initial (rowmin, argmin), pool
__global__ void k_init(const float* __restrict__ X, float* __restrict__ R, int D) {
    int r = blockIdx.x;
    float msim = funflip(g_msim);
    float MAXD = __fmul_rn(funflip(g_mabs), 1000.0f);
    float bv = MAXD; int bbi = 0;
    for (int k = threadIdx.x; k < D; k += blockDim.x) {
        float x = X[(size_t)r * D + k];
        float d = (k == r) ? MAXD : __fsub_rn(msim, x);
        g_Dm[(size_t)r * D + k] = d;
        R[(size_t)r * D + k] = (k == r) ? 1.0f : 0.0f;
        float c = (k > r) ? d : MAXD;
        if (c < bv) { bv = c; bbi = k; }  // ascending k -> leftmost kept
    }
    #pragma unroll
    for (int o = 16; o; o >>= 1) {
        float ov = __shfl_down_sync(~0u, bv, o);
        int oi = __shfl_down_sync(~0u, bbi, o);
        if (ov < bv || (ov == bv && oi < bbi)) { bv = ov; bbi = oi; }
    }
    __shared__ float spv[8]; __shared__ int spi[8];
    int w = threadIdx.x >> 5, l = threadIdx.x & 31;
    if (l == 0) { spv[w] = bv; spi[w] = bbi; }
    __syncthreads();
    if (threadIdx.x == 0) {
        int nw = blockDim.x >> 5;
        for (int i = 1; i < nw; i++)
            if (spv[i] < bv || (spv[i] == bv && spi[i] < bbi)) { bv = spv[i]; bbi = spi[i]; }
        g_vals[r] = bv;
        g_idx[r] = bbi;
        g_pool[r] = r;   // singleton leaf list
    }
}

// Persistent single-block HAC: 3 barriers/iter, leaf-list pool, fused m1-row min,
// owner-masked argmin pre-reduce, warp-parallel final reduce.
__global__ void __launch_bounds__(NT, 1) k_hac(const float* __restrict__ W,
                                               float* __restrict__ R, int D) {
    __shared__ float s_vals[MAXDIM];
    __shared__ int   s_idx[MAXDIM];
    __shared__ float s_cs[MAXDIM];
    __shared__ float s_within[MAXDIM];
    __shared__ float s_energy[MAXDIM];
    __shared__ int   s_off[MAXDIM], s_len[MAXDIM], s_cap[MAXDIM];
    __shared__ int   s_rlist[MAXDIM];
    __shared__ float s_cv[MAXDIM];
    __shared__ int   s_ci[MAXDIM];
    __shared__ unsigned s_amask[MAXDIM / 32];
    __shared__ float s_pv[NW]; __shared__ int s_pi[NW];
    __shared__ float s_mv[NW]; __shared__ int s_mi[NW];
    __shared__ float s_pw[NW];
    __shared__ int s_m1, s_m2, s_take, s_nresc, s_ptop, s_pOff, s_pLen;
    __shared__ float s_cs1, s_cs2, s_ncs;

    const int j = threadIdx.x;
    const int wid = j >> 5, lane = j & 31;
    const float MAXD = __fmul_rn(funflip(g_mabs), 1000.0f);
    const int eb = 4 * j;
    const bool vec4 = ((D & 3) == 0);
    const int NEUT = 0x3FFFFFFF;

    for (int k = j; k < MAXDIM; k += NT) {
        if (k < D) {
            s_vals[k] = g_vals[k]; s_idx[k] = g_idx[k];
            s_cs[k] = 1.0f; s_within[k] = 0.f; s_energy[k] = 0.f;
            s_off[k] = k; s_len[k] = 1; s_cap[k] = 1;
        } else { s_vals[k] = MAXD; s_idx[k] = 0; }
    }
    if (j < MAXDIM / 32) {
        int lo = j * 32; unsigned m = 0u;
        if (D >= lo + 32) m = 0xFFFFFFFFu;
        else if (D > lo) m = (1u << (D - lo)) - 1u;
        s_amask[j] = m;
    }
    if (j == 0) { s_ptop = D; s_take = 0; s_pLen = 0; s_nresc = 0; }
    __syncthreads();

    // ---- prologue: select merge 0
    {
        float v = MAXD; int bi = NEUT;
        #pragma unroll
        for (int q = 0; q < 4; q++) {
            int e = eb + q;
            if (e < D) { float x = s_vals[e]; if (x < v) { v = x; bi = e; } }
        }
        #pragma unroll
        for (int o = 16; o; o >>= 1) {
            float ov = __shfl_down_sync(~0u, v, o);
            int oi = __shfl_down_sync(~0u, bi, o);
            if (ov < v || (ov == v && oi < bi)) { v = ov; bi = oi; }
        }
        if (lane == 0) { s_pv[wid] = v; s_pi[wid] = bi; }
    }
    __syncthreads();
    if (wid == 0) {
        float v = (lane < NW) ? s_pv[lane] : MAXD;
        int bi = (lane < NW) ? s_pi[lane] : NEUT;
        #pragma unroll
        for (int o = 16; o; o >>= 1) {
            float ov = __shfl_down_sync(~0u, v, o);
            int oi = __shfl_down_sync(~0u, bi, o);
            if (ov < v || (ov == v && oi < bi)) { v = ov; bi = oi; }
        }
        if (lane == 0) {
            if (bi >= D) bi = 0;
            int m1 = bi, m2 = s_idx[bi];
            s_m1 = m1; s_m2 = m2;
            float c1 = s_cs[m1], c2 = s_cs[m2];
            float ncs = __fadd_rn(c1, c2);
            s_cs1 = c1; s_cs2 = c2; s_ncs = ncs;
            s_cs[m1] = ncs;
            s_vals[m2] = MAXD;
            s_amask[m2 >> 5] &= ~(1u << (m2 & 31));
        }
    }
    __syncthreads();

    for (int it = 0; it < D - 1; ++it) {
        const int m1 = s_m1, m2 = s_m2;
        const float cs1 = s_cs1, cs2 = s_cs2, ncs = s_ncs;
        const bool inr = (eb < D);

        // ==== Region1: dist loads, prev R-writes, maintenance, fused m1-row min
        float d1[4], d2[4];
        unsigned am = 0u;
        if (inr) {
            am = (s_amask[eb >> 5] >> (eb & 31)) & 0xFu;
            if (vec4) {
                float4 t1 = *(const float4*)&g_Dm[(size_t)m1 * D + eb];
                float4 t2 = *(const float4*)&g_Dm[(size_t)m2 * D + eb];
                d1[0] = t1.x; d1[1] = t1.y; d1[2] = t1.z; d1[3] = t1.w;
                d2[0] = t2.x; d2[1] = t2.y; d2[2] = t2.z; d2[3] = t2.w;
            } else {
                #pragma unroll
                for (int q = 0; q < 4; q++) {
                    int e = eb + q;
                    d1[q] = (e < D) ? g_Dm[(size_t)m1 * D + e] : MAXD;
                    d2[q] = (e < D) ? g_Dm[(size_t)m2 * D + e] : MAXD;
                }
            }
        }

        // R-writes for previous merge (overlaps load latency)
        if (s_take) {
            int poff = s_pOff, plen = s_pLen;
            for (int ai = wid; ai < plen; ai += NW) {
                int a = g_pool[poff + ai];
                float* rp = R + (size_t)a * D;
                for (int b2 = lane; b2 < plen; b2 += 32) rp[g_pool[poff + b2]] = 1.0f;
            }
        }

        unsigned needmask = 0u;
        float nv[4];
        float m1best = MAXD; int m1bi = NEUT;
        #pragma unroll
        for (int q = 0; q < 4; q++) {
            int e = eb + q;
            float v = MAXD;
            if ((am >> q) & 1) {
                if (e != m1) {
                    v = __fdiv_rn(__fadd_rn(__fmul_rn(d1[q], cs1), __fmul_rn(d2[q], cs2)), ncs);
                    float vold = s_vals[e]; int iold = s_idx[e];
                    if (iold == m2) needmask |= 1u << q;
                    else if (m1 > e) {
                        if (iold == m1) {
                            if (v <= vold) s_vals[e] = v; else needmask |= 1u << q;
                        } else {
                            if (v < vold) { s_vals[e] = v; s_idx[e] = m1; }
                            else if (v == vold && m1 < iold) s_idx[e] = m1;
                        }
                    }
                    if (e > m1 && v < m1best) { m1best = v; m1bi = e; }  // leftmost col
                }
            }
            nv[q] = v;
        }
        if (inr) {
            if (vec4) {
                float4 t; t.x = nv[0]; t.y = nv[1]; t.z = nv[2]; t.w = nv[3];
                *(float4*)&g_Dm[(size_t)m1 * D + eb] = t;
            } else {
                #pragma unroll
                for (int q = 0; q < 4; q++) {
                    int e = eb + q;
                    if (e < D) g_Dm[(size_t)m1 * D + e] = nv[q];
                }
            }
            #pragma unroll
            for (int q = 0; q < 4; q++) {
                int e = eb + q;
                if (((am >> q) & 1) && e != m1) g_Dm[(size_t)e * D + m1] = nv[q];
            }
        }
        // fused m1-row min partials (whole warp participates)
        #pragma unroll
        for (int o = 16; o; o >>= 1) {
            float ov = __shfl_down_sync(~0u, m1best, o);
            int oi = __shfl_down_sync(~0u, m1bi, o);
            if (ov < m1best || (ov == m1best && oi < m1bi)) { m1best = ov; m1bi = oi; }
        }
        if (lane == 0) { s_mv[wid] = m1best; s_mi[wid] = m1bi; }
        if (needmask) {
            #pragma unroll
            for (int q = 0; q < 4; q++)
                if ((needmask >> q) & 1) { int p = atomicAdd(&s_nresc, 1); s_rlist[p] = eb + q; }
        }
        __syncthreads();   // B1

        // ==== Region2: owner-masked argmin pre-reduce + rescans + pair sum
        {
            float v = MAXD; int bi = NEUT;
            #pragma unroll
            for (int q = 0; q < 4; q++) {
                int e = eb + q;
                if (e < D && !((needmask >> q) & 1) && e != m1) {
                    float x = s_vals[e];
                    if (x < v) { v = x; bi = e; }
                }
            }
            #pragma unroll
            for (int o = 16; o; o >>= 1) {
                float ov = __shfl_down_sync(~0u, v, o);
                int oi = __shfl_down_sync(~0u, bi, o);
                if (ov < v || (ov == v && oi < bi)) { v = ov; bi = oi; }
            }
            if (lane == 0) { s_pv[wid] = v; s_pi[wid] = bi; }
        }
        {
            int nr = s_nresc;
            for (int t = wid; t < nr; t += NW) {
                int r = s_rlist[t];
                float bv = MAXD; int bbi = 0;
                if (vec4) {
                    const float4* row4 = reinterpret_cast<const float4*>(&g_Dm[(size_t)r * D]);
                    float4 qd[8];
                    #pragma unroll
                    for (int c = 0; c < 8; c++) {
                        int k = c * 128 + lane * 4;
                        if (k < D) qd[c] = row4[k >> 2];
                        else { qd[c].x = MAXD; qd[c].y = MAXD; qd[c].z = MAXD; qd[c].w = MAXD; }
                    }
                    #pragma unroll
                    for (int c = 0; c < 8; c++) {
                        int k = c * 128 + lane * 4;
                        unsigned a2 = (k < D) ? (s_amask[k >> 5] >> (k & 31)) : 0u;
                        float f0 = ((a2 & 1u) && k > r)       ? qd[c].x : MAXD;
                        float f1 = ((a2 & 2u) && (k + 1) > r) ? qd[c].y : MAXD;
                        float f2 = ((a2 & 4u) && (k + 2) > r) ? qd[c].z : MAXD;
                        float f3 = ((a2 & 8u) && (k + 3) > r) ? qd[c].w : MAXD;
                        if (f0 < bv) { bv = f0; bbi = k; }
                        if (f1 < bv) { bv = f1; bbi = k + 1; }
                        if (f2 < bv) { bv = f2; bbi = k + 2; }
                        if (f3 < bv) { bv = f3; bbi = k + 3; }
                    }
                } else {
                    const float* row = &g_Dm[(size_t)r * D];
                    for (int k = lane; k < D; k += 32) {
                        int alv = (s_amask[k >> 5] >> (k & 31)) & 1;
                        float vv = (alv && k > r) ? row[k] : MAXD;
                        if (vv < bv) { bv = vv; bbi = k; }
                    }
                }
                #pragma unroll
                for (int o = 16; o; o >>= 1) {
                    float ov = __shfl_down_sync(~0u, bv, o);
                    int oi = __shfl_down_sync(~0u, bbi, o);
                    if (ov < bv || (ov == bv && oi < bbi)) { bv = ov; bbi = oi; }
                }
                if (lane == 0) {
                    s_vals[r] = bv; s_idx[r] = bbi;
                    s_cv[t] = bv; s_ci[t] = r;
                }
            }
        }
        {
            float ps = 0.f;
            int aOff = s_off[m1], aLen = s_len[m1];
            int bOff = s_off[m2], bLen = s_len[m2];
            for (int ia = wid; ia < aLen; ia += NW) {
                int a = g_pool[aOff + ia];
                for (int ib = lane; ib < bLen; ib += 32) {
                    int b = g_pool[bOff + ib];
                    int lo = a < b ? a : b, hi = a < b ? b : a;
                    ps = __fadd_rn(ps, __ldg(&W[(size_t)lo * D + hi]));
                }
            }
            #pragma unroll
            for (int o = 16; o; o >>= 1) ps = __fadd_rn(ps, __shfl_down_sync(~0u, ps, o));
            if (lane == 0) s_pw[wid] = ps;
        }
        __syncthreads();   // B2

        // ==== Region3 (warp 0): reduces + take + pool append + next selection
        if (wid == 0) {
            float cw = (lane < NW) ? s_pw[lane] : 0.f;
            #pragma unroll
            for (int o = 16; o; o >>= 1) cw = __fadd_rn(cw, __shfl_down_sync(~0u, cw, o));

            float mv = (lane < NW) ? s_mv[lane] : MAXD;
            int mi = (lane < NW) ? s_mi[lane] : NEUT;
            #pragma unroll
            for (int o = 16; o; o >>= 1) {
                float ov = __shfl_down_sync(~0u, mv, o);
                int oi = __shfl_down_sync(~0u, mi, o);
                if (ov < mv || (ov == mv && oi < mi)) { mv = ov; mi = oi; }
            }

            float gv = (lane < NW) ? s_pv[lane] : MAXD;
            int gi = (lane < NW) ? s_pi[lane] : NEUT;
            int nr2 = s_nresc;
            for (int t = lane; t < nr2; t += 32) {
                float cv = s_cv[t]; int ci = s_ci[t];
                if (cv < gv || (cv == gv && ci < gi)) { gv = cv; gi = ci; }
            }
            #pragma unroll
            for (int o = 16; o; o >>= 1) {
                float ov = __shfl_down_sync(~0u, gv, o);
                int oi = __shfl_down_sync(~0u, gi, o);
                if (ov < gv || (ov == gv && oi < gi)) { gv = ov; gi = oi; }
            }

            int dst = 0, src = 0, ncopy = 0, dst2 = 0, src2 = 0, ncopy2 = 0;
            if (lane == 0) {
                if (mi >= D) mi = 0;
                s_vals[m1] = mv; s_idx[m1] = mi;
                if (mv < gv || (mv == gv && m1 < gi)) { gv = mv; gi = m1; }
                if (gi >= D) gi = 0;
                // take decision
                float me = __fadd_rn(__fadd_rn(s_within[m1], s_within[m2]), cw);
                float es = __fadd_rn(s_energy[m1], s_energy[m2]);
                int take = (me >= es) ? 1 : 0;
                s_take = take;
                s_within[m1] = me;
                s_energy[m1] = take ? me : es;
                // leaf-list merge plan
                int aLen = s_len[m1], bLen = s_len[m2], lenN = aLen + bLen;
                int aOff = s_off[m1], bOff = s_off[m2];
                if (lenN <= s_cap[m1]) {
                    dst = aOff + aLen; src = bOff; ncopy = bLen;
                } else if (lenN <= s_cap[m2]) {
                    dst = bOff + bLen; src = aOff; ncopy = aLen;
                    s_off[m1] = bOff; s_cap[m1] = s_cap[m2];
                } else {
                    int nc = 1; while (nc < lenN) nc <<= 1;
                    int nb = s_ptop; s_ptop = nb + nc;
                    dst = nb; src = aOff; ncopy = aLen;
                    dst2 = nb + aLen; src2 = bOff; ncopy2 = bLen;
                    s_off[m1] = nb; s_cap[m1] = nc;
                }
                s_len[m1] = lenN;
                s_pOff = s_off[m1]; s_pLen = lenN;
                // next merge selection (last iteration: harmless)
                int n1 = gi, n2 = s_idx[n1];
                s_m1 = n1; s_m2 = n2;
                float c1 = s_cs[n1], c2 = s_cs[n2];
                float nn = __fadd_rn(c1, c2);
                s_cs1 = c1; s_cs2 = c2; s_ncs = nn;
                s_cs[n1] = nn;
                s_vals[n2] = MAXD;
                s_amask[n2 >> 5] &= ~(1u << (n2 & 31));
                s_nresc = 0;
            }
            dst = __shfl_sync(~0u, dst, 0);   src = __shfl_sync(~0u, src, 0);
            ncopy = __shfl_sync(~0u, ncopy, 0);
            dst2 = __shfl_sync(~0u, dst2, 0); src2 = __shfl_sync(~0u, src2, 0);
            ncopy2 = __shfl_sync(~0u, ncopy2, 0);
            for (int t = lane; t < ncopy; t += 32) g_pool[dst + t] = g_pool[src + t];
            for (int t = lane; t < ncopy2; t += 32) g_pool[dst2 + t] = g_pool[src2 + t];
        }
        __syncthreads();   // B3
    }

    // ==== epilogue: R-writes for the final merge
    if (s_take) {
        int poff = s_pOff, plen = s_pLen;
        for (int ai = wid; ai < plen; ai += NW) {
            int a = g_pool[poff + ai];
            float* rp = R + (size_t)a * D;
            for (int b2 = lane; b2 < plen; b2 += 32) rp[g_pool[poff + b2]] = 1.0f;
        }
    }
}

extern "C" void kernel_launch(void* const* d_in, const int* in_sizes, int n_in,
                              void* d_out, int out_size) {
    const float* X = (const float*)d_in[0];
    const float* W = (const float*)d_in[1];
    float* R = (float*)d_out;
    int n = in_sizes[0];
    int D = (int)(sqrt((double)n) + 0.5);
    if (D < 2 || D > MAXDIM) return;

    k_reset<<<1, 1>>>();
    k_maxred<<<256, 256>>>(X, n);
    k_init<<<D, 256>>>(X, R, D);
    k_hac<<<1, NT>>>(W, R, D);
}

// round 13
// speedup vs baseline: 1.1227x; 1.1227x over previous
#include <cuda_runtime.h>
#include <math.h>

#define MAXDIM 1024
#define NT 512
#define NW 16
#define POOLSZ 65536

// Scratch (device globals; no allocation allowed)
__device__ float g_Dm[MAXDIM * MAXDIM];   // symmetric merged-distance matrix
__device__ int   g_pool[POOLSZ];          // leaf-list pool (capacity-doubling extents)
__device__ float g_vals[MAXDIM];
__device__ int   g_idx[MAXDIM];
__device__ unsigned g_msim;               // flip-encoded max(X)
__device__ unsigned g_mabs;               // flip-encoded max|X|

__device__ __forceinline__ unsigned fflip(float f) {
    unsigned u = __float_as_uint(f);
    return (u & 0x80000000u) ? ~u : (u | 0x80000000u);
}
__device__ __forceinline__ float funflip(unsigned u) {
    return __uint_as_float((u & 0x80000000u) ? (u & 0x7FFFFFFFu) : ~u);
}

__global__ void k_reset() { g_msim = 0u; g_mabs = 0u; }

__global__ void k_maxred(const float* __restrict__ X, int n) {
    float mx = -3.402823466e38f, ma = 0.f;
    for (int i = blockIdx.x * blockDim.x + threadIdx.x; i < n; i += gridDim.x * blockDim.x) {
        float x = X[i];
        mx = fmaxf(mx, x);
        ma = fmaxf(ma, fabsf(x));
    }
    #pragma unroll
    for (int o = 16; o; o >>= 1) {
        mx = fmaxf(mx, __shfl_down_sync(~0u, mx, o));
        ma = fmaxf(ma, __shfl_down_sync(~0u, ma, o));
    }
    __shared__ float smx[8], sma[8];
    int w = threadIdx.x >> 5, l = threadIdx.x & 31;
    if (l == 0) { smx[w] = mx; sma[w] = ma; }
    __syncthreads();
    if (threadIdx.x == 0) {
        int nw = blockDim.x >> 5;
        for (int i = 1; i < nw; i++) { mx = fmaxf(mx, smx[i]); ma = fmaxf(ma, sma[i]); }
        atomicMax(&g_msim, fflip(mx));
        atomicMax(&g_mabs, fflip(ma));
    }
}

// One block per row r: build Dsym row, R row (identity), initial (rowmin, argmin), pool
__global__ void k_init(const float* __restrict__ X, float* __restrict__ R, int D) {
    int r = blockIdx.x;
    float msim = funflip(g_msim);
    float MAXD = __fmul_rn(funflip(g_mabs), 1000.0f);
    float bv = MAXD; int bbi = 0;
    for (int k = threadIdx.x; k < D; k += blockDim.x) {
        float x = X[(size_t)r * D + k];
        float d = (k == r) ? MAXD : __fsub_rn(msim, x);
        g_Dm[(size_t)r * D + k] = d;
        R[(size_t)r * D + k] = (k == r) ? 1.0f : 0.0f;
        float c = (k > r) ? d : MAXD;
        if (c < bv) { bv = c; bbi = k; }  // ascending k -> leftmost kept
    }
    #pragma unroll
    for (int o = 16; o; o >>= 1) {
        float ov = __shfl_down_sync(~0u, bv, o);
        int oi = __shfl_down_sync(~0u, bbi, o);
        if (ov < bv || (ov == bv && oi < bbi)) { bv = ov; bbi = oi; }
    }
    __shared__ float spv[8]; __shared__ int spi[8];
    int w = threadIdx.x >> 5, l = threadIdx.x & 31;
    if (l == 0) { spv[w] = bv; spi[w] = bbi; }
    __syncthreads();
    if (threadIdx.x == 0) {
        int nw = blockDim.x >> 5;
        for (int i = 1; i < nw; i++)
            if (spv[i] < bv || (spv[i] == bv && spi[i] < bbi)) { bv = spv[i]; bbi = spi[i]; }
        g_vals[r] = bv;
        g_idx[r] = bbi;
        g_pool[r] = r;   // singleton leaf list
    }
}

// Persistent single-block HAC: NT=512, 3 barriers/iter, pool leaf lists,
// fused m1-row min, owner-masked argmin pre-reduce, warp-0 parallel final reduce.
__global__ void __launch_bounds__(NT, 1) k_hac(const float* __restrict__ W,
                                               float* __restrict__ R, int D) {
    __shared__ float s_vals[MAXDIM];
    __shared__ int   s_idx[MAXDIM];
    __shared__ float s_cs[MAXDIM];
    __shared__ float s_within[MAXDIM];
    __shared__ float s_energy[MAXDIM];
    __shared__ int   s_off[MAXDIM], s_len[MAXDIM], s_cap[MAXDIM];
    __shared__ int   s_rlist[MAXDIM];
    __shared__ float s_cv[MAXDIM];
    __shared__ int   s_ci[MAXDIM];
    __shared__ unsigned s_amask[MAXDIM / 32];
    __shared__ float s_pv[NW]; __shared__ int s_pi[NW];
    __shared__ float s_mv[NW]; __shared__ int s_mi[NW];
    __shared__ float s_pw[NW];
    __shared__ int s_m1, s_m2, s_take, s_nresc, s_ptop, s_pOff, s_pLen;
    __shared__ float s_cs1, s_cs2, s_ncs;

    const int j = threadIdx.x;
    const int wid = j >> 5, lane = j & 31;
    const float MAXD = __fmul_rn(funflip(g_mabs), 1000.0f);
    const int e0 = 2 * j, e1 = 2 * j + 1;
    const bool evenD = ((D & 1) == 0);
    const bool vec4 = ((D & 3) == 0);
    const int NEUT = 0x3FFFFFFF;

    for (int k = j; k < MAXDIM; k += NT) {
        if (k < D) {
            s_vals[k] = g_vals[k]; s_idx[k] = g_idx[k];
            s_cs[k] = 1.0f; s_within[k] = 0.f; s_energy[k] = 0.f;
            s_off[k] = k; s_len[k] = 1; s_cap[k] = 1;
        } else { s_vals[k] = MAXD; s_idx[k] = 0; }
    }
    if (j < MAXDIM / 32) {
        int lo = j * 32; unsigned m = 0u;
        if (D >= lo + 32) m = 0xFFFFFFFFu;
        else if (D > lo) m = (1u << (D - lo)) - 1u;
        s_amask[j] = m;
    }
    if (j == 0) { s_ptop = D; s_take = 0; s_pLen = 0; s_nresc = 0; }
    __syncthreads();

    // ---- prologue: select merge 0
    {
        float v = MAXD; int bi = NEUT;
        if (e0 < D) { float x = s_vals[e0]; if (x < v) { v = x; bi = e0; } }
        if (e1 < D) { float x = s_vals[e1]; if (x < v) { v = x; bi = e1; } }
        #pragma unroll
        for (int o = 16; o; o >>= 1) {
            float ov = __shfl_down_sync(~0u, v, o);
            int oi = __shfl_down_sync(~0u, bi, o);
            if (ov < v || (ov == v && oi < bi)) { v = ov; bi = oi; }
        }
        if (lane == 0) { s_pv[wid] = v; s_pi[wid] = bi; }
    }
    __syncthreads();
    if (wid == 0) {
        float v = (lane < NW) ? s_pv[lane] : MAXD;
        int bi = (lane < NW) ? s_pi[lane] : NEUT;
        #pragma unroll
        for (int o = 16; o; o >>= 1) {
            float ov = __shfl_down_sync(~0u, v, o);
            int oi = __shfl_down_sync(~0u, bi, o);
            if (ov < v || (ov == v && oi < bi)) { v = ov; bi = oi; }
        }
        if (lane == 0) {
            if (bi >= D) bi = 0;
            int m1 = bi, m2 = s_idx[bi];
            s_m1 = m1; s_m2 = m2;
            float c1 = s_cs[m1], c2 = s_cs[m2];
            float ncs = __fadd_rn(c1, c2);
            s_cs1 = c1; s_cs2 = c2; s_ncs = ncs;
            s_cs[m1] = ncs;
            s_vals[m2] = MAXD;
            s_amask[m2 >> 5] &= ~(1u << (m2 & 31));
        }
    }
    __syncthreads();

    for (int it = 0; it < D - 1; ++it) {
        const int m1 = s_m1, m2 = s_m2;
        const float cs1 = s_cs1, cs2 = s_cs2, ncs = s_ncs;
        const bool inr = (e0 < D);

        // ==== Region1: dist loads, prev R-writes, maintenance, fused m1-row min
        float d10 = MAXD, d11 = MAXD, d20 = MAXD, d21 = MAXD;
        unsigned am = 0u;
        if (inr) {
            am = (s_amask[e0 >> 5] >> (e0 & 31)) & 0x3u;
            if (evenD && e1 < D) {
                float2 t1 = *(const float2*)&g_Dm[(size_t)m1 * D + e0];
                float2 t2 = *(const float2*)&g_Dm[(size_t)m2 * D + e0];
                d10 = t1.x; d11 = t1.y; d20 = t2.x; d21 = t2.y;
            } else {
                d10 = g_Dm[(size_t)m1 * D + e0];
                d20 = g_Dm[(size_t)m2 * D + e0];
                if (e1 < D) { d11 = g_Dm[(size_t)m1 * D + e1]; d21 = g_Dm[(size_t)m2 * D + e1]; }
            }
        }

        // R-writes for previous merge (overlaps load latency)
        if (s_take) {
            int poff = s_pOff, plen = s_pLen;
            for (int ai = wid; ai < plen; ai += NW) {
                int a = g_pool[poff + ai];
                float* rp = R + (size_t)a * D;
                for (int b2 = lane; b2 < plen; b2 += 32) rp[g_pool[poff + b2]] = 1.0f;
            }
        }

        unsigned needmask = 0u;
        float nv0 = MAXD, nv1 = MAXD;
        float m1best = MAXD; int m1bi = NEUT;
        if (am & 1u) {
            if (e0 != m1) {
                nv0 = __fdiv_rn(__fadd_rn(__fmul_rn(d10, cs1), __fmul_rn(d20, cs2)), ncs);
                float vold = s_vals[e0]; int iold = s_idx[e0];
                if (iold == m2) needmask |= 1u;
                else if (m1 > e0) {
                    if (iold == m1) {
                        if (nv0 <= vold) s_vals[e0] = nv0; else needmask |= 1u;
                    } else {
                        if (nv0 < vold) { s_vals[e0] = nv0; s_idx[e0] = m1; }
                        else if (nv0 == vold && m1 < iold) s_idx[e0] = m1;
                    }
                }
                if (e0 > m1 && nv0 < m1best) { m1best = nv0; m1bi = e0; }
            }
        }
        if (am & 2u) {
            if (e1 != m1) {
                nv1 = __fdiv_rn(__fadd_rn(__fmul_rn(d11, cs1), __fmul_rn(d21, cs2)), ncs);
                float vold = s_vals[e1]; int iold = s_idx[e1];
                if (iold == m2) needmask |= 2u;
                else if (m1 > e1) {
                    if (iold == m1) {
                        if (nv1 <= vold) s_vals[e1] = nv1; else needmask |= 2u;
                    } else {
                        if (nv1 < vold) { s_vals[e1] = nv1; s_idx[e1] = m1; }
                        else if (nv1 == vold && m1 < iold) s_idx[e1] = m1;
                    }
                }
                // e1 > m1 case for m1-row min (leftmost: e0 checked first)
                if (e1 > m1 && nv1 < m1best) { m1best = nv1; m1bi = e1; }
            }
        }
        if (inr) {
            if (evenD && e1 < D) {
                float2 t; t.x = nv0; t.y = nv1;
                *(float2*)&g_Dm[(size_t)m1 * D + e0] = t;
            } else {
                g_Dm[(size_t)m1 * D + e0] = nv0;
                if (e1 < D) g_Dm[(size_t)m1 * D + e1] = nv1;
            }
            if ((am & 1u) && e0 != m1) g_Dm[(size_t)e0 * D + m1] = nv0;
            if ((am & 2u) && e1 != m1) g_Dm[(size_t)e1 * D + m1] = nv1;
        }
        // fused m1-row min partials
        #pragma unroll
        for (int o = 16; o; o >>= 1) {
            float ov = __shfl_down_sync(~0u, m1best, o);
            int oi = __shfl_down_sync(~0u, m1bi, o);
            if (ov < m1best || (ov == m1best && oi < m1bi)) { m1best = ov; m1bi = oi; }
        }
        if (lane == 0) { s_mv[wid] = m1best; s_mi[wid] = m1bi; }
        if (needmask & 1u) { int p = atomicAdd(&s_nresc, 1); s_rlist[p] = e0; }
        if (needmask & 2u) { int p = atomicAdd(&s_nresc, 1); s_rlist[p] = e1; }
        __syncthreads();   // B1

        // ==== Region2: owner-masked argmin pre-reduce + rescans + pair sum
        {
            float v = MAXD; int bi = NEUT;
            if (e0 < D && !(needmask & 1u) && e0 != m1) {
                float x = s_vals[e0];
                if (x < v) { v = x; bi = e0; }
            }
            if (e1 < D && !(needmask & 2u) && e1 != m1) {
                float x = s_vals[e1];
                if (x < v) { v = x; bi = e1; }
            }
            #pragma unroll
            for (int o = 16; o; o >>= 1) {
                float ov = __shfl_down_sync(~0u, v, o);
                int oi = __shfl_down_sync(~0u, bi, o);
                if (ov < v || (ov == v && oi < bi)) { v = ov; bi = oi; }
            }
            if (lane == 0) { s_pv[wid] = v; s_pi[wid] = bi; }
        }
        {
            int nr = s_nresc;
            for (int t = wid; t < nr; t += NW) {
                int r = s_rlist[t];
                float bv = MAXD; int bbi = 0;
                if (vec4) {
                    const float4* row4 = reinterpret_cast<const float4*>(&g_Dm[(size_t)r * D]);
                    float4 qd[8];
                    #pragma unroll
                    for (int c = 0; c < 8; c++) {
                        int k = c * 128 + lane * 4;
                        if (k < D) qd[c] = row4[k >> 2];
                        else { qd[c].x = MAXD; qd[c].y = MAXD; qd[c].z = MAXD; qd[c].w = MAXD; }
                    }
                    #pragma unroll
                    for (int c = 0; c < 8; c++) {
                        int k = c * 128 + lane * 4;
                        unsigned a2 = (k < D) ? (s_amask[k >> 5] >> (k & 31)) : 0u;
                        float f0 = ((a2 & 1u) && k > r)       ? qd[c].x : MAXD;
                        float f1 = ((a2 & 2u) && (k + 1) > r) ? qd[c].y : MAXD;
                        float f2 = ((a2 & 4u) && (k + 2) > r) ? qd[c].z : MAXD;
                        float f3 = ((a2 & 8u) && (k + 3) > r) ? qd[c].w : MAXD;
                        if (f0 < bv) { bv = f0; bbi = k; }
                        if (f1 < bv) { bv = f1; bbi = k + 1; }
                        if (f2 < bv) { bv = f2; bbi = k + 2; }
                        if (f3 < bv) { bv = f3; bbi = k + 3; }
                    }
                } else {
                    const float* row = &g_Dm[(size_t)r * D];
                    for (int k = lane; k < D; k += 32) {
                        int alv = (s_amask[k >> 5] >> (k & 31)) & 1;
                        float vv = (alv && k > r) ? row[k] : MAXD;
                        if (vv < bv) { bv = vv; bbi = k; }
                    }
                }
                #pragma unroll
                for (int o = 16; o; o >>= 1) {
                    float ov = __shfl_down_sync(~0u, bv, o);
                    int oi = __shfl_down_sync(~0u, bbi, o);
                    if (ov < bv || (ov == bv && oi < bbi)) { bv = ov; bbi = oi; }
                }
                if (lane == 0) {
                    s_vals[r] = bv; s_idx[r] = bbi;
                    s_cv[t] = bv; s_ci[t] = r;
                }
            }
        }
        {
            float ps = 0.f;
            int aOff = s_off[m1], aLen = s_len[m1];
            int bOff = s_off[m2], bLen = s_len[m2];
            for (int ia = wid; ia < aLen; ia += NW) {
                int a = g_pool[aOff + ia];
                for (int ib = lane; ib < bLen; ib += 32) {
                    int b = g_pool[bOff + ib];
                    int lo = a < b ? a : b, hi = a < b ? b : a;
                    ps = __fadd_rn(ps, __ldg(&W[(size_t)lo * D + hi]));
                }
            }
            #pragma unroll
            for (int o = 16; o; o >>= 1) ps = __fadd_rn(ps, __shfl_down_sync(~0u, ps, o));
            if (lane == 0) s_pw[wid] = ps;
        }
        __syncthreads();   // B2

        // ==== Region3 (warp 0): reduces + take + pool append + next selection
        if (wid == 0) {
            float cw = (lane < NW) ? s_pw[lane] : 0.f;
            #pragma unroll
            for (int o = 16; o; o >>= 1) cw = __fadd_rn(cw, __shfl_down_sync(~0u, cw, o));

            float mv = (lane < NW) ? s_mv[lane] : MAXD;
            int mi = (lane < NW) ? s_mi[lane] : NEUT;
            #pragma unroll
            for (int o = 16; o; o >>= 1) {
                float ov = __shfl_down_sync(~0u, mv, o);
                int oi = __shfl_down_sync(~0u, mi, o);
                if (ov < mv || (ov == mv && oi < mi)) { mv = ov; mi = oi; }
            }

            float gv = (lane < NW) ? s_pv[lane] : MAXD;
            int gi = (lane < NW) ? s_pi[lane] : NEUT;
            int nr2 = s_nresc;
            for (int t = lane; t < nr2; t += 32) {
                float cv = s_cv[t]; int ci = s_ci[t];
                if (cv < gv || (cv == gv && ci < gi)) { gv = cv; gi = ci; }
            }
            #pragma unroll
            for (int o = 16; o; o >>= 1) {
                float ov = __shfl_down_sync(~0u, gv, o);
                int oi = __shfl_down_sync(~0u, gi, o);
                if (ov < gv || (ov == gv && oi < gi)) { gv = ov; gi = oi; }
            }

            int dst = 0, src = 0, ncopy = 0, dst2 = 0, src2 = 0, ncopy2 = 0;
            if (lane == 0) {
                if (mi >= D) mi = 0;
                s_vals[m1] = mv; s_idx[m1] = mi;
                if (mv < gv || (mv == gv && m1 < gi)) { gv = mv; gi = m1; }
                if (gi >= D) gi = 0;
                // take decision
                float me = __fadd_rn(__fadd_rn(s_within[m1], s_within[m2]), cw);
                float es = __fadd_rn(s_energy[m1], s_energy[m2]);
                int take = (me >= es) ? 1 : 0;
                s_take = take;
                s_within[m1] = me;
                s_energy[m1] = take ? me : es;
                // leaf-list merge plan
                int aLen = s_len[m1], bLen = s_len[m2], lenN = aLen + bLen;
                int aOff = s_off[m1], bOff = s_off[m2];
                if (lenN <= s_cap[m1]) {
                    dst = aOff + aLen; src = bOff; ncopy = bLen;
                } else if (lenN <= s_cap[m2]) {
                    dst = bOff + bLen; src = aOff; ncopy = aLen;
                    s_off[m1] = bOff; s_cap[m1] = s_cap[m2];
                } else {
                    int nc = 1; while (nc < lenN) nc <<= 1;
                    int nb = s_ptop; s_ptop = nb + nc;
                    dst = nb; src = aOff; ncopy = aLen;
                    dst2 = nb + aLen; src2 = bOff; ncopy2 = bLen;
                    s_off[m1] = nb; s_cap[m1] = nc;
                }
                s_len[m1] = lenN;
                s_pOff = s_off[m1]; s_pLen = lenN;
                // next merge selection (last iteration: harmless)
                int n1 = gi, n2 = s_idx[n1];
                s_m1 = n1; s_m2 = n2;
                float c1 = s_cs[n1], c2 = s_cs[n2];
                float nn = __fadd_rn(c1, c2);
                s_cs1 = c1; s_cs2 = c2; s_ncs = nn;
                s_cs[n1] = nn;
                s_vals[n2] = MAXD;
                s_amask[n2 >> 5] &= ~(1u << (n2 & 31));
                s_nresc = 0;
            }
            dst = __shfl_sync(~0u, dst, 0);   src = __shfl_sync(~0u, src, 0);
            ncopy = __shfl_sync(~0u, ncopy, 0);
            dst2 = __shfl_sync(~0u, dst2, 0); src2 = __shfl_sync(~0u, src2, 0);
            ncopy2 = __shfl_sync(~0u, ncopy2, 0);
            for (int t = lane; t < ncopy; t += 32) g_pool[dst + t] = g_pool[src + t];
            for (int t = lane; t < ncopy2; t += 32) g_pool[dst2 + t] = g_pool[src2 + t];
        }
        __syncthreads();   // B3
    }

    // ==== epilogue: R-writes for the final merge
    if (s_take) {
        int poff = s_pOff, plen = s_pLen;
        for (int ai = wid; ai < plen; ai += NW) {
            int a = g_pool[poff + ai];
            float* rp = R + (size_t)a * D;
            for (int b2 = lane; b2 < plen; b2 += 32) rp[g_pool[poff + b2]] = 1.0f;
        }
    }
}

extern "C" void kernel_launch(void* const* d_in, const int* in_sizes, int n_in,
                              void* d_out, int out_size) {
    const float* X = (const float*)d_in[0];
    const float* W = (const float*)d_in[1];
    float* R = (float*)d_out;
    int n = in_sizes[0];
    int D = (int)(sqrt((double)n) + 0.5);
    if (D < 2 || D > MAXDIM) return;

    k_reset<<<1, 1>>>();
    k_maxred<<<256, 256>>>(X, n);
    k_init<<<D, 256>>>(X, R, D);
    k_hac<<<1, NT>>>(W, R, D);
}